// round 1
// baseline (speedup 1.0000x reference)
#include <cuda_runtime.h>
#include <math.h>

// Problem constants
#define BATCH 8
#define NCH   384
#define HH    56
#define WW    56
#define HWSZ  3136      // 56*56
#define NKV   784       // 28*28
#define HK    28
#define NG    4
#define GC    96
#define NH    8
#define HC    48

#define YSZ   (BATCH*NCH*HWSZ)     // 9633792
#define PSZ   (BATCH*NG*NKV*2)     // 50176

// Scratch (allocation-free rule: __device__ globals)
static __device__ float g_q  [BATCH*NCH*HWSZ];
static __device__ float g_xs [BATCH*NCH*NKV];
static __device__ float g_k  [BATCH*NCH*NKV];
static __device__ float g_v  [BATCH*NCH*NKV];
static __device__ float g_att[BATCH*NCH*HWSZ];
static __device__ float g_pos[BATCH*NG*NKV*2];

// ---------------------------------------------------------------------------
// Generic batched GEMM with bias: C[z] = A(MxK) * B[z](KxN) + bias
// A row-major (M,K) shared across batch; B[z],C[z] row-major (K,N)/(M,N).
// BM=64, BN=64, BK=16, 256 threads, 4x4 register tile per thread.
// ---------------------------------------------------------------------------
__global__ __launch_bounds__(256)
void gemm_bias(const float* __restrict__ A, const float* __restrict__ Bsrc,
               const float* __restrict__ bias, float* __restrict__ C,
               int M, int K, int N)
{
    __shared__ float As[16][64];
    __shared__ float Bs[16][64];
    const float* Bp = Bsrc + (size_t)blockIdx.z * K * N;
    float*       Cp = C    + (size_t)blockIdx.z * M * N;
    int m0 = blockIdx.y * 64, n0 = blockIdx.x * 64;
    int tid = threadIdx.x;
    int tm = (tid >> 4) << 2;       // 0..60
    int tn = (tid & 15) << 2;       // 0..60

    float acc[4][4];
#pragma unroll
    for (int i = 0; i < 4; i++)
#pragma unroll
        for (int j = 0; j < 4; j++) acc[i][j] = 0.f;

    for (int k0 = 0; k0 < K; k0 += 16) {
#pragma unroll
        for (int i = 0; i < 4; i++) {
            int idx = tid + i * 256;          // 0..1023
            int m = idx >> 4, k = idx & 15;   // 64x16
            As[k][m] = A[(size_t)(m0 + m) * K + k0 + k];
        }
#pragma unroll
        for (int i = 0; i < 4; i++) {
            int idx = tid + i * 256;
            int k = idx >> 6, n = idx & 63;   // 16x64
            Bs[k][n] = (n0 + n < N) ? Bp[(size_t)(k0 + k) * N + n0 + n] : 0.f;
        }
        __syncthreads();
#pragma unroll
        for (int k = 0; k < 16; k++) {
            float4 a4 = *reinterpret_cast<const float4*>(&As[k][tm]);
            float4 b4 = *reinterpret_cast<const float4*>(&Bs[k][tn]);
            float a[4] = {a4.x, a4.y, a4.z, a4.w};
            float b[4] = {b4.x, b4.y, b4.z, b4.w};
#pragma unroll
            for (int i = 0; i < 4; i++)
#pragma unroll
                for (int j = 0; j < 4; j++) acc[i][j] += a[i] * b[j];
        }
        __syncthreads();
    }
#pragma unroll
    for (int i = 0; i < 4; i++) {
        int m = m0 + tm + i;
        float bb = bias[m];
#pragma unroll
        for (int j = 0; j < 4; j++) {
            int n = n0 + tn + j;
            if (n < N) Cp[(size_t)m * N + n] = acc[i][j] + bb;
        }
    }
}

// ---------------------------------------------------------------------------
// Offset network: depthwise 3x3 stride-2 conv + channel LayerNorm + exact GELU
// + 1x1 conv to 2 ch + tanh*(1/27) + reference points -> pos (yx).
// One block (128 threads) per (bg, i, j). Also writes pos/ref outputs.
// ---------------------------------------------------------------------------
__global__ __launch_bounds__(128)
void offset_net(const float* __restrict__ q,
                const float* __restrict__ dw_w, const float* __restrict__ dw_b,
                const float* __restrict__ ln_g, const float* __restrict__ ln_b,
                const float* __restrict__ pw_w,
                float* __restrict__ pos, float* __restrict__ pos_out,
                float* __restrict__ ref_out)
{
    int blk = blockIdx.x;            // bg*784 + i*28 + j
    int bg = blk / NKV;
    int ij = blk - bg * NKV;
    int i = ij / HK, j = ij - i * HK;
    int b = bg >> 2, g = bg & 3;
    int c = threadIdx.x;

    __shared__ float red[128];

    float h = 0.f;
    if (c < GC) {
        const float* qc = q + ((size_t)(b * NCH + g * GC + c)) * HWSZ;
        const float* w = dw_w + c * 9;
        int y0 = 2 * i - 1, x0 = 2 * j - 1;
#pragma unroll
        for (int ky = 0; ky < 3; ky++) {
            int y = y0 + ky;
            if (y < 0 || y >= HH) continue;
#pragma unroll
            for (int kx = 0; kx < 3; kx++) {
                int x = x0 + kx;
                if (x < 0 || x >= WW) continue;
                h += w[ky * 3 + kx] * qc[y * WW + x];
            }
        }
        h += dw_b[c];
    }
    // mean
    red[c] = (c < GC) ? h : 0.f; __syncthreads();
    for (int s = 64; s > 0; s >>= 1) { if (c < s) red[c] += red[c + s]; __syncthreads(); }
    float mu = red[0] * (1.f / GC); __syncthreads();
    // var
    float d = (c < GC) ? (h - mu) : 0.f;
    red[c] = d * d; __syncthreads();
    for (int s = 64; s > 0; s >>= 1) { if (c < s) red[c] += red[c + s]; __syncthreads(); }
    float var = red[0] * (1.f / GC); __syncthreads();

    float hn = 0.f;
    if (c < GC) {
        hn = d * rsqrtf(var + 1e-5f) * ln_g[c] + ln_b[c];
        hn = 0.5f * hn * (1.f + erff(hn * 0.70710678118654752f));   // exact GELU
    }
    // offset_y = <pw_w[0,:], hn>, offset_x = <pw_w[1,:], hn>
    red[c] = (c < GC) ? pw_w[c] * hn : 0.f; __syncthreads();
    for (int s = 64; s > 0; s >>= 1) { if (c < s) red[c] += red[c + s]; __syncthreads(); }
    float offy = red[0]; __syncthreads();
    red[c] = (c < GC) ? pw_w[GC + c] * hn : 0.f; __syncthreads();
    for (int s = 64; s > 0; s >>= 1) { if (c < s) red[c] += red[c + s]; __syncthreads(); }
    float offx = red[0];

    if (c == 0) {
        float ry = (0.5f + (float)i) * (1.f / 27.f) * 2.f - 1.f;
        float rx = (0.5f + (float)j) * (1.f / 27.f) * 2.f - 1.f;
        float py = tanhf(offy) * (1.f / 27.f) + ry;
        float px = tanhf(offx) * (1.f / 27.f) + rx;
        size_t o = ((size_t)bg * NKV + ij) * 2;
        pos[o] = py;     pos[o + 1] = px;
        pos_out[o] = py; pos_out[o + 1] = px;
        ref_out[o] = ry; ref_out[o + 1] = rx;
    }
}

// ---------------------------------------------------------------------------
// Bilinear grid sample (align_corners=True, zeros padding), pos in (y,x).
// One thread per (bg, c, p); threads ordered with p fastest for coalesced store.
// ---------------------------------------------------------------------------
__global__ __launch_bounds__(256)
void grid_sample_k(const float* __restrict__ x, const float* __restrict__ pos,
                   float* __restrict__ xs)
{
    int bg = blockIdx.y;
    int b = bg >> 2, g = bg & 3;
    int idx = blockIdx.x * 256 + threadIdx.x;   // < 96*784
    int c = idx / NKV, p = idx - c * NKV;

    float py = pos[((size_t)bg * NKV + p) * 2];
    float px = pos[((size_t)bg * NKV + p) * 2 + 1];
    float gx = (px + 1.f) * 0.5f * (WW - 1);
    float gy = (py + 1.f) * 0.5f * (HH - 1);
    float x0f = floorf(gx), y0f = floorf(gy);
    int x0 = (int)x0f, y0 = (int)y0f;
    float wx1 = gx - x0f, wx0 = 1.f - wx1;
    float wy1 = gy - y0f, wy0 = 1.f - wy1;

    const float* img = x + ((size_t)(b * NCH + g * GC + c)) * HWSZ;

    float v00 = 0.f, v01 = 0.f, v10 = 0.f, v11 = 0.f;
    bool xv0 = (x0 >= 0) && (x0 < WW);
    bool xv1 = (x0 + 1 >= 0) && (x0 + 1 < WW);
    bool yv0 = (y0 >= 0) && (y0 < HH);
    bool yv1 = (y0 + 1 >= 0) && (y0 + 1 < HH);
    if (xv0 && yv0) v00 = img[y0 * WW + x0];
    if (xv1 && yv0) v01 = img[y0 * WW + x0 + 1];
    if (xv0 && yv1) v10 = img[(y0 + 1) * WW + x0];
    if (xv1 && yv1) v11 = img[(y0 + 1) * WW + x0 + 1];

    float acc = v00 * wx0 * wy0 + v01 * wx1 * wy0 + v10 * wx0 * wy1 + v11 * wx1 * wy1;
    xs[((size_t)(b * NCH + g * GC + c)) * NKV + p] = acc;
}

// ---------------------------------------------------------------------------
// Attention: per (head, 16-query tile). Two-pass with logits in smem
// (row stride 785 to avoid bank conflicts). k and v tiled through smem.
// ---------------------------------------------------------------------------
#define TM 16
#define TNK 64
#define LSTR 785
#define ATT_SMEM ((TM*LSTR + HC*TM + HC*TNK) * 4)   // 65600 bytes

__global__ __launch_bounds__(256)
void attention_k(const float* __restrict__ q, const float* __restrict__ k,
                 const float* __restrict__ v, float* __restrict__ out)
{
    extern __shared__ float sm[];
    float* logits = sm;                 // TM * LSTR
    float* qs     = sm + TM * LSTR;     // HC * TM
    float* kv     = qs + HC * TM;       // HC * TNK

    int head = blockIdx.y;
    int b = head >> 3, hh = head & 7;
    const float* qp = q + ((size_t)(b * NCH + hh * HC)) * HWSZ;
    const float* kp = k + ((size_t)(b * NCH + hh * HC)) * NKV;
    const float* vp = v + ((size_t)(b * NCH + hh * HC)) * NKV;
    float*       op = out + ((size_t)(b * NCH + hh * HC)) * HWSZ;
    int m0 = blockIdx.x * TM;
    int tid = threadIdx.x;
    const float scale = 0.14433756729740643f;   // 1/sqrt(48)

    // load q tile (48 x 16)
    for (int idx = tid; idx < HC * TM; idx += 256) {
        int c = idx / TM, mi = idx - c * TM;
        qs[c * TM + mi] = qp[(size_t)c * HWSZ + m0 + mi];
    }
    __syncthreads();

    // Pass 1: logits = scale * q^T k
    {
        int mi = tid >> 4;
        int nb = (tid & 15) << 2;
        for (int n0 = 0; n0 < NKV; n0 += TNK) {
            int tn = min(TNK, NKV - n0);
            for (int idx = tid; idx < HC * TNK; idx += 256) {
                int c = idx >> 6, n = idx & 63;
                kv[c * TNK + n] = (n < tn) ? kp[(size_t)c * NKV + n0 + n] : 0.f;
            }
            __syncthreads();
            if (nb < tn) {
                float a0 = 0.f, a1 = 0.f, a2 = 0.f, a3 = 0.f;
#pragma unroll
                for (int c = 0; c < HC; c++) {
                    float a = qs[c * TM + mi];
                    float4 kk = *reinterpret_cast<const float4*>(&kv[c * TNK + nb]);
                    a0 += a * kk.x; a1 += a * kk.y; a2 += a * kk.z; a3 += a * kk.w;
                }
                float* lr = &logits[mi * LSTR + n0 + nb];
                lr[0] = a0 * scale; lr[1] = a1 * scale; lr[2] = a2 * scale; lr[3] = a3 * scale;
            }
            __syncthreads();
        }
    }

    // Softmax per row (8 warps, 2 rows each)
    {
        int warp = tid >> 5, lane = tid & 31;
        for (int mi = warp; mi < TM; mi += 8) {
            float* lr = &logits[mi * LSTR];
            float mx = -1e30f;
            for (int n = lane; n < NKV; n += 32) mx = fmaxf(mx, lr[n]);
#pragma unroll
            for (int o = 16; o > 0; o >>= 1) mx = fmaxf(mx, __shfl_xor_sync(0xffffffffu, mx, o));
            float sum = 0.f;
            for (int n = lane; n < NKV; n += 32) {
                float e = __expf(lr[n] - mx);
                lr[n] = e; sum += e;
            }
#pragma unroll
            for (int o = 16; o > 0; o >>= 1) sum += __shfl_xor_sync(0xffffffffu, sum, o);
            float inv = 1.f / sum;
            for (int n = lane; n < NKV; n += 32) lr[n] *= inv;
        }
    }
    __syncthreads();

    // Pass 2: out[c, mi] = sum_n p[mi, n] * v[c, n]
    {
        int mi = tid & 15;
        int cb = tid >> 4;          // 0..15 ; handles c = cb, cb+16, cb+32
        float acc0 = 0.f, acc1 = 0.f, acc2 = 0.f;
        for (int n0 = 0; n0 < NKV; n0 += TNK) {
            int tn = min(TNK, NKV - n0);
            for (int idx = tid; idx < HC * TNK; idx += 256) {
                int c = idx >> 6, n = idx & 63;
                kv[c * TNK + n] = (n < tn) ? vp[(size_t)c * NKV + n0 + n] : 0.f;
            }
            __syncthreads();
            const float* lr = &logits[mi * LSTR + n0];
#pragma unroll 4
            for (int n = 0; n < tn; n++) {
                float p = lr[n];
                acc0 += p * kv[cb * TNK + n];
                acc1 += p * kv[(cb + 16) * TNK + n];
                acc2 += p * kv[(cb + 32) * TNK + n];
            }
            __syncthreads();
        }
        op[(size_t)cb * HWSZ + m0 + mi]        = acc0;
        op[(size_t)(cb + 16) * HWSZ + m0 + mi] = acc1;
        op[(size_t)(cb + 32) * HWSZ + m0 + mi] = acc2;
    }
}

// ---------------------------------------------------------------------------
extern "C" void kernel_launch(void* const* d_in, const int* in_sizes, int n_in,
                              void* d_out, int out_size)
{
    const float* x   = (const float*)d_in[0];
    const float* Wq  = (const float*)d_in[1];
    const float* bq  = (const float*)d_in[2];
    const float* Wk  = (const float*)d_in[3];
    const float* bk  = (const float*)d_in[4];
    const float* Wv  = (const float*)d_in[5];
    const float* bv  = (const float*)d_in[6];
    const float* Wo  = (const float*)d_in[7];
    const float* bo  = (const float*)d_in[8];
    const float* dww = (const float*)d_in[9];
    const float* dwb = (const float*)d_in[10];
    const float* lng = (const float*)d_in[11];
    const float* lnb = (const float*)d_in[12];
    const float* pww = (const float*)d_in[13];
    float* out = (float*)d_out;

    float *q, *xs, *k, *v, *att, *pos;
    cudaGetSymbolAddress((void**)&q,   g_q);
    cudaGetSymbolAddress((void**)&xs,  g_xs);
    cudaGetSymbolAddress((void**)&k,   g_k);
    cudaGetSymbolAddress((void**)&v,   g_v);
    cudaGetSymbolAddress((void**)&att, g_att);
    cudaGetSymbolAddress((void**)&pos, g_pos);

    cudaFuncSetAttribute(attention_k, cudaFuncAttributeMaxDynamicSharedMemorySize, ATT_SMEM);

    dim3 gbig((HWSZ + 63) / 64, NCH / 64, BATCH);   // 49 x 6 x 8
    dim3 gsml((NKV + 63) / 64, NCH / 64, BATCH);    // 13 x 6 x 8

    // 1) q = Wq x + bq
    gemm_bias<<<gbig, 256>>>(Wq, x, bq, q, NCH, NCH, HWSZ);
    // 2) offset net -> pos (also writes pos/ref outputs)
    offset_net<<<BATCH * NG * NKV, 128>>>(q, dww, dwb, lng, lnb, pww,
                                          pos, out + YSZ, out + YSZ + PSZ);
    // 3) grid sample -> xs
    grid_sample_k<<<dim3((GC * NKV) / 256, BATCH * NG), 256>>>(x, pos, xs);
    // 4) k, v
    gemm_bias<<<gsml, 256>>>(Wk, xs, bk, k, NCH, NCH, NKV);
    gemm_bias<<<gsml, 256>>>(Wv, xs, bv, v, NCH, NCH, NKV);
    // 5) attention -> att
    attention_k<<<dim3(HWSZ / TM, BATCH * NH), 256, ATT_SMEM>>>(q, k, v, att);
    // 6) y = Wo att + bo
    gemm_bias<<<gbig, 256>>>(Wo, att, bo, out, NCH, NCH, HWSZ);
}